// round 12
// baseline (speedup 1.0000x reference)
#include <cuda_runtime.h>
#include <cstdint>

#define D 128
#define H 16
#define B 8192
#define NTOT 2048              // GEMM N = D*H

#define AS_STRIDE 132          // padded K stride in words: bank = (4*r + c) % 32, conflict-free

// g_WeffT[n][k] = rna_tf32( A[k, n/H] * W1[n/H, k, n%H] )
__device__ float g_WeffT[NTOT * D];

__device__ __forceinline__ float f2tf32(float x) {
    float y; asm("cvt.rna.tf32.f32 %0, %1;" : "=f"(y) : "f"(x)); return y;
}

__device__ __forceinline__ void mma1688(float* c, const uint32_t* a, const uint32_t* b) {
    asm volatile("mma.sync.aligned.m16n8k8.row.col.f32.tf32.tf32.f32 "
        "{%0,%1,%2,%3}, {%4,%5,%6,%7}, {%8,%9}, {%0,%1,%2,%3};"
        : "+f"(c[0]), "+f"(c[1]), "+f"(c[2]), "+f"(c[3])
        : "r"(a[0]), "r"(a[1]), "r"(a[2]), "r"(a[3]), "r"(b[0]), "r"(b[1]));
}

// ---------------------------------------------------------------------------
// Setup: A (gumbel-softmax sigmoid) -> out tail; WeffT[n][v] = rna(A[v,i]*W1[i,v,h])
// ---------------------------------------------------------------------------
__global__ void setup_kernel(const float* __restrict__ logits,
                             const float* __restrict__ temperature,
                             const float* __restrict__ gumbel,
                             const float* __restrict__ W1,
                             float* __restrict__ outA) {
    int idx = blockIdx.x * blockDim.x + threadIdx.x;   // n*128 + v
    int v = idx & 127;
    int n = idx >> 7;
    int i = n >> 4;
    int h = n & 15;

    float T  = temperature[0];
    float l  = logits[v * D + i];
    float g0 = gumbel[(v * D + i) * 2 + 0];
    float g1 = gumbel[(v * D + i) * 2 + 1];
    float A = 1.0f / (1.0f + expf((g0 - g1 - 2.0f * l) / T));
    if (v == i) A = 0.0f;

    g_WeffT[idx] = f2tf32(A * W1[i * (D * H) + v * H + h]);
    if (h == 0) outA[v * D + i] = A;
}

// ---------------------------------------------------------------------------
// Tile loader: gmem row-major [128][128] f32 -> smem [row][k] with stride 132.
// float4 loads + float4 stores (132 % 4 == 0 keeps 16B alignment).
// ---------------------------------------------------------------------------
__device__ __forceinline__ void load_tile(const float* __restrict__ src,
                                          float* __restrict__ dst,
                                          int tid, bool cvt) {
    #pragma unroll 4
    for (int it = 0; it < 16; it++) {
        int idx = it * 256 + tid;          // 4096 float4s
        int r = idx >> 5;                  // row 0..127
        int c = idx & 31;                  // float4 col 0..31
        float4 v = reinterpret_cast<const float4*>(src)[idx];
        if (cvt) {
            v.x = f2tf32(v.x); v.y = f2tf32(v.y);
            v.z = f2tf32(v.z); v.w = f2tf32(v.w);
        }
        *reinterpret_cast<float4*>(&dst[r * AS_STRIDE + c * 4]) = v;
    }
}

// ---------------------------------------------------------------------------
// Main: per-CTA 128(M) x 128(N) x 128(K) tf32 mma.sync GEMM + fused MLP epilogue.
// 8 warps = 2(M) x 4(N); each warp 64x32 via 4x4 m16n8k8 tiles.
// ---------------------------------------------------------------------------
__global__ void __launch_bounds__(256, 1)
dag_mma_kernel(const float* __restrict__ X,
               const float* __restrict__ b1,
               const float* __restrict__ W2,
               const float* __restrict__ b2,
               float* __restrict__ out) {
    extern __shared__ float smem[];
    float* As = smem;                          // [128][AS_STRIDE]  X tile (m-major)
    float* Bs = smem + 128 * AS_STRIDE;        // [128][AS_STRIDE]  WeffT tile (n-major)

    const int tid   = threadIdx.x;
    const int lane  = tid & 31;
    const int wid   = tid >> 5;
    const int warp_m = wid & 1;                // 0..1 (64 rows each)
    const int warp_n = wid >> 1;               // 0..3 (32 n-cols each)
    const int r  = lane >> 2;                  // 0..7
    const int cq = lane & 3;                   // 0..3

    const int nblk  = blockIdx.x;              // 0..15
    const int mblk  = blockIdx.y;              // 0..63
    const int mbase = mblk * 128;
    const int nbase = nblk * 128;
    const int ivar0 = nblk * 8;

    load_tile(X + (size_t)mbase * D, As, tid, true);
    load_tile(g_WeffT + (size_t)nbase * D, Bs, tid, false);
    __syncthreads();

    float acc[4][4][4];
    #pragma unroll
    for (int mt = 0; mt < 4; mt++)
        #pragma unroll
        for (int nt = 0; nt < 4; nt++)
            #pragma unroll
            for (int e = 0; e < 4; e++) acc[mt][nt][e] = 0.0f;

    #pragma unroll 2
    for (int ks = 0; ks < 16; ks++) {
        const int k0 = ks * 8;
        uint32_t a[4][4], bf[4][2];
        #pragma unroll
        for (int mt = 0; mt < 4; mt++) {
            const float* ap = &As[(warp_m * 64 + mt * 16 + r) * AS_STRIDE + k0 + cq];
            a[mt][0] = __float_as_uint(ap[0]);
            a[mt][1] = __float_as_uint(ap[8 * AS_STRIDE]);
            a[mt][2] = __float_as_uint(ap[4]);
            a[mt][3] = __float_as_uint(ap[8 * AS_STRIDE + 4]);
        }
        #pragma unroll
        for (int nt = 0; nt < 4; nt++) {
            const float* bp = &Bs[(warp_n * 32 + nt * 8 + r) * AS_STRIDE + k0 + cq];
            bf[nt][0] = __float_as_uint(bp[0]);
            bf[nt][1] = __float_as_uint(bp[4]);
        }
        #pragma unroll
        for (int mt = 0; mt < 4; mt++)
            #pragma unroll
            for (int nt = 0; nt < 4; nt++)
                mma1688(acc[mt][nt], a[mt], bf[nt]);
    }

    // ---- fused epilogue: relu(+b1) . W2 + b2, reduced across the 4-lane k-groups
    // C frag: c0=(row r, col 2cq), c1=(r, 2cq+1), c2=(r+8, 2cq), c3=(r+8, 2cq+1)
    #pragma unroll
    for (int j = 0; j < 2; j++) {                      // 2 variables per warp
        const int i = ivar0 + warp_n * 2 + j;
        float b1v[4], w2v[4];
        #pragma unroll
        for (int nt2 = 0; nt2 < 2; nt2++)
            #pragma unroll
            for (int e = 0; e < 2; e++) {
                int h = nt2 * 8 + 2 * cq + e;
                b1v[nt2 * 2 + e] = __ldg(&b1[i * H + h]);
                w2v[nt2 * 2 + e] = __ldg(&W2[i * H + h]);
            }
        const float bias = __ldg(&b2[i]);
        #pragma unroll
        for (int mt = 0; mt < 4; mt++) {
            #pragma unroll
            for (int half = 0; half < 2; half++) {     // row r (+0) or r+8
                float p = 0.0f;
                #pragma unroll
                for (int nt2 = 0; nt2 < 2; nt2++) {
                    const int nt = 2 * j + nt2;
                    p = fmaf(fmaxf(acc[mt][nt][half * 2 + 0] + b1v[nt2 * 2 + 0], 0.0f),
                             w2v[nt2 * 2 + 0], p);
                    p = fmaf(fmaxf(acc[mt][nt][half * 2 + 1] + b1v[nt2 * 2 + 1], 0.0f),
                             w2v[nt2 * 2 + 1], p);
                }
                p += __shfl_xor_sync(0xffffffffu, p, 1);
                p += __shfl_xor_sync(0xffffffffu, p, 2);
                if (cq == 0) {
                    int row = mbase + warp_m * 64 + mt * 16 + half * 8 + r;
                    out[(size_t)row * D + i] = p + bias;
                }
            }
        }
    }
}

// ---------------------------------------------------------------------------
extern "C" void kernel_launch(void* const* d_in, const int* in_sizes, int n_in,
                              void* d_out, int out_size) {
    const float* X      = (const float*)d_in[0];
    const float* logits = (const float*)d_in[1];
    const float* temp   = (const float*)d_in[2];
    const float* gumbel = (const float*)d_in[3];
    const float* W1     = (const float*)d_in[4];
    const float* b1     = (const float*)d_in[5];
    const float* W2     = (const float*)d_in[6];
    const float* b2     = (const float*)d_in[7];
    float* out = (float*)d_out;
    (void)in_sizes; (void)n_in; (void)out_size;

    setup_kernel<<<(NTOT * D) / 256, 256>>>(logits, temp, gumbel, W1, out + (size_t)B * D);

    size_t smem = (size_t)(2 * 128 * AS_STRIDE) * sizeof(float);   // 135168 B
    cudaFuncSetAttribute(dag_mma_kernel,
                         cudaFuncAttributeMaxDynamicSharedMemorySize, (int)smem);
    dag_mma_kernel<<<dim3(16, 64), 256, smem>>>(X, b1, W2, b2, out);
}

// round 13
// speedup vs baseline: 1.0045x; 1.0045x over previous
#include <cuda_runtime.h>
#include <cstdint>

#define D 128
#define H 16
#define B 8192
#define NTOT 2048              // GEMM N = D*H

#define AS_STRIDE 132          // padded K stride in words: bank = (4*r + c) % 32, conflict-free

// g_WeffT[n][k] = rna_tf32( A[k, n/H] * W1[n/H, k, n%H] )
__device__ float g_WeffT[NTOT * D];

__device__ __forceinline__ float f2tf32(float x) {
    float y; asm("cvt.rna.tf32.f32 %0, %1;" : "=f"(y) : "f"(x)); return y;
}

__device__ __forceinline__ void mma1688(float* c, const uint32_t* a, const uint32_t* b) {
    asm volatile("mma.sync.aligned.m16n8k8.row.col.f32.tf32.tf32.f32 "
        "{%0,%1,%2,%3}, {%4,%5,%6,%7}, {%8,%9}, {%0,%1,%2,%3};"
        : "+f"(c[0]), "+f"(c[1]), "+f"(c[2]), "+f"(c[3])
        : "r"(a[0]), "r"(a[1]), "r"(a[2]), "r"(a[3]), "r"(b[0]), "r"(b[1]));
}

// ---------------------------------------------------------------------------
// Setup: A (gumbel-softmax sigmoid) -> out tail; WeffT[n][v] = rna(A[v,i]*W1[i,v,h])
// ---------------------------------------------------------------------------
__global__ void setup_kernel(const float* __restrict__ logits,
                             const float* __restrict__ temperature,
                             const float* __restrict__ gumbel,
                             const float* __restrict__ W1,
                             float* __restrict__ outA) {
    int idx = blockIdx.x * blockDim.x + threadIdx.x;   // n*128 + v
    int v = idx & 127;
    int n = idx >> 7;
    int i = n >> 4;
    int h = n & 15;

    float T  = temperature[0];
    float l  = logits[v * D + i];
    float g0 = gumbel[(v * D + i) * 2 + 0];
    float g1 = gumbel[(v * D + i) * 2 + 1];
    float A = 1.0f / (1.0f + expf((g0 - g1 - 2.0f * l) / T));
    if (v == i) A = 0.0f;

    g_WeffT[idx] = f2tf32(A * W1[i * (D * H) + v * H + h]);
    if (h == 0) outA[v * D + i] = A;
}

// ---------------------------------------------------------------------------
// Tile loader: gmem row-major [128][128] f32 -> smem [row][k] with stride 132.
// float4 loads + float4 stores (132 % 4 == 0 keeps 16B alignment).
// ---------------------------------------------------------------------------
__device__ __forceinline__ void load_tile(const float* __restrict__ src,
                                          float* __restrict__ dst,
                                          int tid, bool cvt) {
    #pragma unroll 4
    for (int it = 0; it < 16; it++) {
        int idx = it * 256 + tid;          // 4096 float4s
        int r = idx >> 5;                  // row 0..127
        int c = idx & 31;                  // float4 col 0..31
        float4 v = reinterpret_cast<const float4*>(src)[idx];
        if (cvt) {
            v.x = f2tf32(v.x); v.y = f2tf32(v.y);
            v.z = f2tf32(v.z); v.w = f2tf32(v.w);
        }
        *reinterpret_cast<float4*>(&dst[r * AS_STRIDE + c * 4]) = v;
    }
}

// ---------------------------------------------------------------------------
// Main: per-CTA 128(M) x 128(N) x 128(K) tf32 mma.sync GEMM + fused MLP epilogue.
// 8 warps = 2(M) x 4(N); each warp 64x32 via 4x4 m16n8k8 tiles.
// ---------------------------------------------------------------------------
__global__ void __launch_bounds__(256, 1)
dag_mma_kernel(const float* __restrict__ X,
               const float* __restrict__ b1,
               const float* __restrict__ W2,
               const float* __restrict__ b2,
               float* __restrict__ out) {
    extern __shared__ float smem[];
    float* As = smem;                          // [128][AS_STRIDE]  X tile (m-major)
    float* Bs = smem + 128 * AS_STRIDE;        // [128][AS_STRIDE]  WeffT tile (n-major)

    const int tid   = threadIdx.x;
    const int lane  = tid & 31;
    const int wid   = tid >> 5;
    const int warp_m = wid & 1;                // 0..1 (64 rows each)
    const int warp_n = wid >> 1;               // 0..3 (32 n-cols each)
    const int r  = lane >> 2;                  // 0..7
    const int cq = lane & 3;                   // 0..3

    const int nblk  = blockIdx.x;              // 0..15
    const int mblk  = blockIdx.y;              // 0..63
    const int mbase = mblk * 128;
    const int nbase = nblk * 128;
    const int ivar0 = nblk * 8;

    load_tile(X + (size_t)mbase * D, As, tid, true);
    load_tile(g_WeffT + (size_t)nbase * D, Bs, tid, false);
    __syncthreads();

    float acc[4][4][4];
    #pragma unroll
    for (int mt = 0; mt < 4; mt++)
        #pragma unroll
        for (int nt = 0; nt < 4; nt++)
            #pragma unroll
            for (int e = 0; e < 4; e++) acc[mt][nt][e] = 0.0f;

    #pragma unroll 2
    for (int ks = 0; ks < 16; ks++) {
        const int k0 = ks * 8;
        uint32_t a[4][4], bf[4][2];
        #pragma unroll
        for (int mt = 0; mt < 4; mt++) {
            const float* ap = &As[(warp_m * 64 + mt * 16 + r) * AS_STRIDE + k0 + cq];
            a[mt][0] = __float_as_uint(ap[0]);
            a[mt][1] = __float_as_uint(ap[8 * AS_STRIDE]);
            a[mt][2] = __float_as_uint(ap[4]);
            a[mt][3] = __float_as_uint(ap[8 * AS_STRIDE + 4]);
        }
        #pragma unroll
        for (int nt = 0; nt < 4; nt++) {
            const float* bp = &Bs[(warp_n * 32 + nt * 8 + r) * AS_STRIDE + k0 + cq];
            bf[nt][0] = __float_as_uint(bp[0]);
            bf[nt][1] = __float_as_uint(bp[4]);
        }
        #pragma unroll
        for (int mt = 0; mt < 4; mt++)
            #pragma unroll
            for (int nt = 0; nt < 4; nt++)
                mma1688(acc[mt][nt], a[mt], bf[nt]);
    }

    // ---- fused epilogue: relu(+b1) . W2 + b2, reduced across the 4-lane k-groups
    // C frag: c0=(row r, col 2cq), c1=(r, 2cq+1), c2=(r+8, 2cq), c3=(r+8, 2cq+1)
    #pragma unroll
    for (int j = 0; j < 2; j++) {                      // 2 variables per warp
        const int i = ivar0 + warp_n * 2 + j;
        float b1v[4], w2v[4];
        #pragma unroll
        for (int nt2 = 0; nt2 < 2; nt2++)
            #pragma unroll
            for (int e = 0; e < 2; e++) {
                int h = nt2 * 8 + 2 * cq + e;
                b1v[nt2 * 2 + e] = __ldg(&b1[i * H + h]);
                w2v[nt2 * 2 + e] = __ldg(&W2[i * H + h]);
            }
        const float bias = __ldg(&b2[i]);
        #pragma unroll
        for (int mt = 0; mt < 4; mt++) {
            #pragma unroll
            for (int half = 0; half < 2; half++) {     // row r (+0) or r+8
                float p = 0.0f;
                #pragma unroll
                for (int nt2 = 0; nt2 < 2; nt2++) {
                    const int nt = 2 * j + nt2;
                    p = fmaf(fmaxf(acc[mt][nt][half * 2 + 0] + b1v[nt2 * 2 + 0], 0.0f),
                             w2v[nt2 * 2 + 0], p);
                    p = fmaf(fmaxf(acc[mt][nt][half * 2 + 1] + b1v[nt2 * 2 + 1], 0.0f),
                             w2v[nt2 * 2 + 1], p);
                }
                p += __shfl_xor_sync(0xffffffffu, p, 1);
                p += __shfl_xor_sync(0xffffffffu, p, 2);
                if (cq == 0) {
                    int row = mbase + warp_m * 64 + mt * 16 + half * 8 + r;
                    out[(size_t)row * D + i] = p + bias;
                }
            }
        }
    }
}

// ---------------------------------------------------------------------------
extern "C" void kernel_launch(void* const* d_in, const int* in_sizes, int n_in,
                              void* d_out, int out_size) {
    const float* X      = (const float*)d_in[0];
    const float* logits = (const float*)d_in[1];
    const float* temp   = (const float*)d_in[2];
    const float* gumbel = (const float*)d_in[3];
    const float* W1     = (const float*)d_in[4];
    const float* b1     = (const float*)d_in[5];
    const float* W2     = (const float*)d_in[6];
    const float* b2     = (const float*)d_in[7];
    float* out = (float*)d_out;
    (void)in_sizes; (void)n_in; (void)out_size;

    setup_kernel<<<(NTOT * D) / 256, 256>>>(logits, temp, gumbel, W1, out + (size_t)B * D);

    size_t smem = (size_t)(2 * 128 * AS_STRIDE) * sizeof(float);   // 135168 B
    cudaFuncSetAttribute(dag_mma_kernel,
                         cudaFuncAttributeMaxDynamicSharedMemorySize, (int)smem);
    dag_mma_kernel<<<dim3(16, 64), 256, smem>>>(X, b1, W2, b2, out);
}

// round 14
// speedup vs baseline: 1.0136x; 1.0091x over previous
#include <cuda_runtime.h>
#include <cstdint>

#define D 128
#define H 16
#define B 8192
#define NTOT 2048              // GEMM N = D*H

#define AS_STRIDE 132          // padded K stride in words: bank = (4*r + c) % 32, conflict-free

// g_WeffT[n][k] = rna_tf32( A[k, n/H] * W1[n/H, k, n%H] )
__device__ float g_WeffT[NTOT * D];

__device__ __forceinline__ float f2tf32(float x) {
    float y; asm("cvt.rna.tf32.f32 %0, %1;" : "=f"(y) : "f"(x)); return y;
}

__device__ __forceinline__ void mma1688(float* c, const uint32_t* a, const uint32_t* b) {
    asm volatile("mma.sync.aligned.m16n8k8.row.col.f32.tf32.tf32.f32 "
        "{%0,%1,%2,%3}, {%4,%5,%6,%7}, {%8,%9}, {%0,%1,%2,%3};"
        : "+f"(c[0]), "+f"(c[1]), "+f"(c[2]), "+f"(c[3])
        : "r"(a[0]), "r"(a[1]), "r"(a[2]), "r"(a[3]), "r"(b[0]), "r"(b[1]));
}

// ---------------------------------------------------------------------------
// Setup: A (gumbel-softmax sigmoid) -> out tail; WeffT[n][v] = rna(A[v,i]*W1[i,v,h])
// ---------------------------------------------------------------------------
__global__ void setup_kernel(const float* __restrict__ logits,
                             const float* __restrict__ temperature,
                             const float* __restrict__ gumbel,
                             const float* __restrict__ W1,
                             float* __restrict__ outA) {
    int idx = blockIdx.x * blockDim.x + threadIdx.x;   // n*128 + v
    int v = idx & 127;
    int n = idx >> 7;
    int i = n >> 4;
    int h = n & 15;

    float T  = temperature[0];
    float l  = logits[v * D + i];
    float g0 = gumbel[(v * D + i) * 2 + 0];
    float g1 = gumbel[(v * D + i) * 2 + 1];
    float A = 1.0f / (1.0f + expf((g0 - g1 - 2.0f * l) / T));
    if (v == i) A = 0.0f;

    g_WeffT[idx] = f2tf32(A * W1[i * (D * H) + v * H + h]);
    if (h == 0) outA[v * D + i] = A;
}

// ---------------------------------------------------------------------------
// Tile loader: gmem row-major [128][128] f32 -> smem [row][k] with stride 132.
// float4 loads + float4 stores (132 % 4 == 0 keeps 16B alignment).
// ---------------------------------------------------------------------------
__device__ __forceinline__ void load_tile(const float* __restrict__ src,
                                          float* __restrict__ dst,
                                          int tid, bool cvt) {
    #pragma unroll 4
    for (int it = 0; it < 16; it++) {
        int idx = it * 256 + tid;          // 4096 float4s
        int r = idx >> 5;                  // row 0..127
        int c = idx & 31;                  // float4 col 0..31
        float4 v = reinterpret_cast<const float4*>(src)[idx];
        if (cvt) {
            v.x = f2tf32(v.x); v.y = f2tf32(v.y);
            v.z = f2tf32(v.z); v.w = f2tf32(v.w);
        }
        *reinterpret_cast<float4*>(&dst[r * AS_STRIDE + c * 4]) = v;
    }
}

// ---------------------------------------------------------------------------
// Main: per-CTA 128(M) x 128(N) x 128(K) tf32 mma.sync GEMM + fused MLP epilogue.
// 8 warps = 2(M) x 4(N); each warp 64x32 via 4x4 m16n8k8 tiles.
// ---------------------------------------------------------------------------
__global__ void __launch_bounds__(256, 1)
dag_mma_kernel(const float* __restrict__ X,
               const float* __restrict__ b1,
               const float* __restrict__ W2,
               const float* __restrict__ b2,
               float* __restrict__ out) {
    extern __shared__ float smem[];
    float* As = smem;                          // [128][AS_STRIDE]  X tile (m-major)
    float* Bs = smem + 128 * AS_STRIDE;        // [128][AS_STRIDE]  WeffT tile (n-major)

    const int tid   = threadIdx.x;
    const int lane  = tid & 31;
    const int wid   = tid >> 5;
    const int warp_m = wid & 1;                // 0..1 (64 rows each)
    const int warp_n = wid >> 1;               // 0..3 (32 n-cols each)
    const int r  = lane >> 2;                  // 0..7
    const int cq = lane & 3;                   // 0..3

    const int nblk  = blockIdx.x;              // 0..15
    const int mblk  = blockIdx.y;              // 0..63
    const int mbase = mblk * 128;
    const int nbase = nblk * 128;
    const int ivar0 = nblk * 8;

    load_tile(X + (size_t)mbase * D, As, tid, true);
    load_tile(g_WeffT + (size_t)nbase * D, Bs, tid, false);
    __syncthreads();

    float acc[4][4][4];
    #pragma unroll
    for (int mt = 0; mt < 4; mt++)
        #pragma unroll
        for (int nt = 0; nt < 4; nt++)
            #pragma unroll
            for (int e = 0; e < 4; e++) acc[mt][nt][e] = 0.0f;

    #pragma unroll 2
    for (int ks = 0; ks < 16; ks++) {
        const int k0 = ks * 8;
        uint32_t a[4][4], bf[4][2];
        #pragma unroll
        for (int mt = 0; mt < 4; mt++) {
            const float* ap = &As[(warp_m * 64 + mt * 16 + r) * AS_STRIDE + k0 + cq];
            a[mt][0] = __float_as_uint(ap[0]);
            a[mt][1] = __float_as_uint(ap[8 * AS_STRIDE]);
            a[mt][2] = __float_as_uint(ap[4]);
            a[mt][3] = __float_as_uint(ap[8 * AS_STRIDE + 4]);
        }
        #pragma unroll
        for (int nt = 0; nt < 4; nt++) {
            const float* bp = &Bs[(warp_n * 32 + nt * 8 + r) * AS_STRIDE + k0 + cq];
            bf[nt][0] = __float_as_uint(bp[0]);
            bf[nt][1] = __float_as_uint(bp[4]);
        }
        #pragma unroll
        for (int mt = 0; mt < 4; mt++)
            #pragma unroll
            for (int nt = 0; nt < 4; nt++)
                mma1688(acc[mt][nt], a[mt], bf[nt]);
    }

    // ---- fused epilogue: relu(+b1) . W2 + b2, reduced across the 4-lane k-groups
    // C frag: c0=(row r, col 2cq), c1=(r, 2cq+1), c2=(r+8, 2cq), c3=(r+8, 2cq+1)
    #pragma unroll
    for (int j = 0; j < 2; j++) {                      // 2 variables per warp
        const int i = ivar0 + warp_n * 2 + j;
        float b1v[4], w2v[4];
        #pragma unroll
        for (int nt2 = 0; nt2 < 2; nt2++)
            #pragma unroll
            for (int e = 0; e < 2; e++) {
                int h = nt2 * 8 + 2 * cq + e;
                b1v[nt2 * 2 + e] = __ldg(&b1[i * H + h]);
                w2v[nt2 * 2 + e] = __ldg(&W2[i * H + h]);
            }
        const float bias = __ldg(&b2[i]);
        #pragma unroll
        for (int mt = 0; mt < 4; mt++) {
            #pragma unroll
            for (int half = 0; half < 2; half++) {     // row r (+0) or r+8
                float p = 0.0f;
                #pragma unroll
                for (int nt2 = 0; nt2 < 2; nt2++) {
                    const int nt = 2 * j + nt2;
                    p = fmaf(fmaxf(acc[mt][nt][half * 2 + 0] + b1v[nt2 * 2 + 0], 0.0f),
                             w2v[nt2 * 2 + 0], p);
                    p = fmaf(fmaxf(acc[mt][nt][half * 2 + 1] + b1v[nt2 * 2 + 1], 0.0f),
                             w2v[nt2 * 2 + 1], p);
                }
                p += __shfl_xor_sync(0xffffffffu, p, 1);
                p += __shfl_xor_sync(0xffffffffu, p, 2);
                if (cq == 0) {
                    int row = mbase + warp_m * 64 + mt * 16 + half * 8 + r;
                    out[(size_t)row * D + i] = p + bias;
                }
            }
        }
    }
}

// ---------------------------------------------------------------------------
extern "C" void kernel_launch(void* const* d_in, const int* in_sizes, int n_in,
                              void* d_out, int out_size) {
    const float* X      = (const float*)d_in[0];
    const float* logits = (const float*)d_in[1];
    const float* temp   = (const float*)d_in[2];
    const float* gumbel = (const float*)d_in[3];
    const float* W1     = (const float*)d_in[4];
    const float* b1     = (const float*)d_in[5];
    const float* W2     = (const float*)d_in[6];
    const float* b2     = (const float*)d_in[7];
    float* out = (float*)d_out;
    (void)in_sizes; (void)n_in; (void)out_size;

    setup_kernel<<<(NTOT * D) / 256, 256>>>(logits, temp, gumbel, W1, out + (size_t)B * D);

    size_t smem = (size_t)(2 * 128 * AS_STRIDE) * sizeof(float);   // 135168 B
    cudaFuncSetAttribute(dag_mma_kernel,
                         cudaFuncAttributeMaxDynamicSharedMemorySize, (int)smem);
    dag_mma_kernel<<<dim3(16, 64), 256, smem>>>(X, b1, W2, b2, out);
}